// round 11
// baseline (speedup 1.0000x reference)
#include <cuda_runtime.h>
#include <cuda.h>
#include <cuda_fp16.h>
#include <cstdint>

#define NM 16384
__device__ __half g_XH [(size_t)NM*1024];
__device__ float  g_G  [(size_t)NM*4096];
__device__ __half g_T0 [(size_t)16416*1024];
__device__ __half g_T1 [(size_t)16416*1024];
__device__ __half g_W0h[(size_t)4096*1024];
__device__ __half g_W1h[(size_t)4096*1024];
__device__ __half g_Wh0[(size_t)4096*1024];
__device__ __half g_Wh1[(size_t)4096*1024];
__device__ unsigned g_cnt0, g_cnt1;

__device__ __forceinline__ uint32_t s32(const void* p){ return (uint32_t)__cvta_generic_to_shared(p); }
__device__ __forceinline__ void cp16(void* s, const void* g){
  asm volatile("cp.async.cg.shared.global [%0],[%1],16;"::"r"(s32(s)),"l"(g));
}
__device__ __forceinline__ void cpc(){ asm volatile("cp.async.commit_group;"); }
template<int N> __device__ __forceinline__ void cpw(){ asm volatile("cp.async.wait_group %0;"::"n"(N)); }
__device__ __forceinline__ unsigned ldacq(const unsigned* p){ unsigned v; asm volatile("ld.acquire.gpu.u32 %0,[%1];":"=r"(v):"l"(p)); return v; }
__device__ __forceinline__ void arrive(unsigned* p){ asm volatile("red.release.gpu.global.add.u32 [%0],1;"::"l"(p)); }
__device__ __forceinline__ void mbar_init(uint64_t* m, unsigned c){
  asm volatile("mbarrier.init.shared.b64 [%0],%1;"::"r"(s32(m)),"r"(c):"memory");
}
__device__ __forceinline__ void mexpect(uint64_t* m, unsigned bytes){
  asm volatile("mbarrier.arrive.expect_tx.shared.b64 _,[%0],%1;"::"r"(s32(m)),"r"(bytes):"memory");
}
__device__ __forceinline__ void mwait(uint64_t* m, int ph){
  uint32_t a=s32(m);
  asm volatile("{\n\t.reg .pred P;\nLW%=:\n\tmbarrier.try_wait.parity.shared::cta.b64 P,[%0],%1,0x989680;\n\t@P bra LD%=;\n\tbra LW%=;\nLD%=:\n\t}"::"r"(a),"r"(ph):"memory");
}
__device__ __forceinline__ void tma2d(uint32_t smem, const void* map, int x, int y, uint64_t* mb){
  asm volatile("cp.async.bulk.tensor.2d.shared::cta.global.tile.mbarrier::complete_tx::bytes [%0],[%1,{%2,%3}],[%4];"
    ::"r"(smem),"l"(map),"r"(x),"r"(y),"r"(s32(mb)):"memory");
}
__device__ __forceinline__ void fpa(){ asm volatile("fence.proxy.async;"); }
__device__ __forceinline__ void mma16(float* d, const uint32_t* a, const uint32_t* b){
  asm volatile("mma.sync.aligned.m16n8k16.row.col.f32.f16.f16.f32 {%0,%1,%2,%3},{%4,%5,%6,%7},{%8,%9},{%0,%1,%2,%3};"
    :"+f"(d[0]),"+f"(d[1]),"+f"(d[2]),"+f"(d[3])
    :"r"(a[0]),"r"(a[1]),"r"(a[2]),"r"(a[3]),"r"(b[0]),"r"(b[1]));
}
__device__ __forceinline__ float sigm(float x){ return 1.f/(1.f+__expf(-x)); }

__global__ void k_init(const float* __restrict__ h0){
  int i=blockIdx.x*256+threadIdx.x;
  if(i==0){ g_cnt0=0u; g_cnt1=0u; }
  __half v=__float2half_rn(h0[i]);
  if(i<32768) g_T0[i]=v; else g_T1[i-32768]=v;
}

__global__ void k_gather(const int* __restrict__ tok, const float* __restrict__ emb){
  size_t e=((size_t)blockIdx.x*256+threadIdx.x)*4;
  int row=(int)(e>>10), col=(int)(e&1023);
  float4 v=*(const float4*)(emb+(size_t)tok[row]*1024+col);
  __half2* p=(__half2*)(g_XH+e);
  p[0]=__floats2half2_rn(v.x,v.y); p[1]=__floats2half2_rn(v.z,v.w);
}

__global__ void k_prepw(const float* __restrict__ w0, const float* __restrict__ w1,
                        const float* __restrict__ wh0, const float* __restrict__ wh1){
  size_t e=((size_t)blockIdx.x*256+threadIdx.x)*4;
  float4 a=*(const float4*)(w0+e);
  ((__half2*)(g_W0h+e))[0]=__floats2half2_rn(a.x,a.y);
  ((__half2*)(g_W0h+e))[1]=__floats2half2_rn(a.z,a.w);
  float4 b=*(const float4*)(w1+e);
  ((__half2*)(g_W1h+e))[0]=__floats2half2_rn(b.x,b.y);
  ((__half2*)(g_W1h+e))[1]=__floats2half2_rn(b.z,b.w);
  float4 c=*(const float4*)(wh0+e);
  ((__half2*)(g_Wh0+e))[0]=__floats2half2_rn(c.x,c.y);
  ((__half2*)(g_Wh0+e))[1]=__floats2half2_rn(c.z,c.w);
  float4 d=*(const float4*)(wh1+e);
  ((__half2*)(g_Wh1+e))[0]=__floats2half2_rn(d.x,d.y);
  ((__half2*)(g_Wh1+e))[1]=__floats2half2_rn(d.z,d.w);
}

// ---- GEMM fp16: C[16384,4096] = A[16384,1024] @ W[4096,1024]^T + (b1+b2) ----
__global__ void __launch_bounds__(256,2) k_gemm(
  const __grid_constant__ CUtensorMap mA, const __grid_constant__ CUtensorMap mW,
  int yoff, const float* __restrict__ b1, const float* __restrict__ b2,
  float* __restrict__ C){
  extern __shared__ char smraw[];
  char* base=(char*)((((uintptr_t)smraw)+1023)&~(uintptr_t)1023);
  uint32_t* sA=(uint32_t*)base;            // 3 x 16KB (128 rows x 64 halves)
  uint32_t* sB=(uint32_t*)(base+49152);    // 3 x 16KB
  uint64_t* mb=(uint64_t*)(base+98304);
  const int tid=threadIdx.x, lane=tid&31, wid=tid>>5;
  const int wm=wid>>1, wn=wid&1, gid=lane>>2, tig=lane&3;
  const int bm=blockIdx.y, bn=blockIdx.x;
  const void* pA=(const void*)&mA; const void* pW=(const void*)&mW;
  uint32_t sa0=s32(sA), sb0=s32(sB);
  if(tid==0){ mbar_init(mb+0,1); mbar_init(mb+1,1); mbar_init(mb+2,1); fpa(); }
  __syncthreads();
  auto issue=[&](int ks){
    if(tid==0){
      int s=ks%3;
      mexpect(mb+s,32768);
      tma2d(sa0+s*16384, pA, ks*64, bm*128+yoff, mb+s);
      tma2d(sb0+s*16384, pW, ks*64, bn*128,      mb+s);
    }
  };
  issue(0); issue(1); issue(2);
  float acc[2][8][4];
  #pragma unroll
  for(int i=0;i<2;i++)
    #pragma unroll
    for(int j=0;j<8;j++)
      #pragma unroll
      for(int k=0;k<4;k++) acc[i][j][k]=0.f;
  for(int ks=0;ks<16;ks++){
    int s=ks%3;
    mwait(mb+s,(ks/3)&1);
    const uint32_t* cA=sA+s*4096; const uint32_t* cB=sB+s*4096;
    #pragma unroll
    for(int kk=0;kk<4;kk++){
      int c0=(((kk*2)^gid)<<2)+tig, c1=(((kk*2+1)^gid)<<2)+tig;
      uint32_t a[2][4], b[8][2];
      #pragma unroll
      for(int mt=0;mt<2;mt++){
        int r0=wm*32+mt*16+gid;
        a[mt][0]=cA[r0*32+c0]; a[mt][1]=cA[(r0+8)*32+c0];
        a[mt][2]=cA[r0*32+c1]; a[mt][3]=cA[(r0+8)*32+c1];
      }
      #pragma unroll
      for(int nt=0;nt<8;nt++){
        int n0=wn*64+nt*8+gid;
        b[nt][0]=cB[n0*32+c0]; b[nt][1]=cB[n0*32+c1];
      }
      #pragma unroll
      for(int mt=0;mt<2;mt++)
        #pragma unroll
        for(int nt=0;nt<8;nt++) mma16(acc[mt][nt], a[mt], b[nt]);
    }
    __syncthreads();
    if(ks+3<16) issue(ks+3);
  }
  #pragma unroll
  for(int nt=0;nt<8;nt++){
    int n=bn*128+wn*64+nt*8+tig*2;
    float bb0=b1[n]+b2[n], bb1=b1[n+1]+b2[n+1];
    #pragma unroll
    for(int mt=0;mt<2;mt++){
      size_t m0=(size_t)bm*128+wm*32+mt*16+gid;
      *(float2*)(C+m0*4096+n)    =make_float2(acc[mt][nt][0]+bb0, acc[mt][nt][1]+bb1);
      *(float2*)(C+(m0+8)*4096+n)=make_float2(acc[mt][nt][2]+bb0, acc[mt][nt][3]+bb1);
    }
  }
}

// ---- persistent recurrence (fp16, 4 buffers, lean sync) --------------------
__global__ void __launch_bounds__(256,1) k_rec(
  const __grid_constant__ CUtensorMap mH,
  const __half* __restrict__ Whh, const float* __restrict__ c0l,
  const float* __restrict__ G, __half* __restrict__ Th,
  float* __restrict__ histf,
  float* __restrict__ hFl, float* __restrict__ cFl, unsigned* cnt){
  extern __shared__ char smraw[];
  char* base=(char*)((((uintptr_t)smraw)+1023)&~(uintptr_t)1023);
  uint32_t* Hs=(uint32_t*)base;            // 4 x 16KB h buffers
  __half*   Ws=(__half*)(base+65536);      // 32 x 1032 halves (66048B)
  float*    Red=(float*)(base+131584);     // 32KB
  float*    Gs =(float*)(base+164352);     // 32 x 36 floats (4608B)
  uint64_t* mb =(uint64_t*)(base+168960);  // 4 mbarriers
  const int tid=threadIdx.x, lane=tid&31, w=tid>>5;
  const int gid=lane>>2, tig=lane&3, u0=blockIdx.x*8;
  const int cb=tid>>3, cu=tid&7;
  const void* pH=(const void*)&mH;
  uint32_t hs0=s32(Hs);

  if(tid==0){
    mbar_init(mb+0,1); mbar_init(mb+1,1); mbar_init(mb+2,1); mbar_init(mb+3,1);
    fpa();
  }
  #pragma unroll 4
  for(int i=0;i<16;i++){
    int idx=i*256+tid, r=idx>>7, q=idx&127;
    cp16(Ws+r*1032+q*8, Whh+(size_t)((r>>3)*1024+u0+(r&7))*1024+q*8);
  }
  cpc(); cpw<0>();
  float creg=c0l[cb*1024+u0+cu];
  __syncthreads();

  float acc[2][4][4];
  auto comp=[&](int c){
    const uint32_t* Hc=Hs+c*4096;         // words
    #pragma unroll
    for(int kk=0;kk<2;kk++){
      int q=2*w+kk, s=q>>2, off=(q&3)*2;
      int c0=((off^gid)<<2)+tig, c1=(((off+1)^gid)<<2)+tig;
      uint32_t a[2][4], b[4][2];
      #pragma unroll
      for(int mt=0;mt<2;mt++){
        int r0=mt*16+gid;
        a[mt][0]=Hc[s*1024+r0*32+c0]; a[mt][1]=Hc[s*1024+(r0+8)*32+c0];
        a[mt][2]=Hc[s*1024+r0*32+c1]; a[mt][3]=Hc[s*1024+(r0+8)*32+c1];
      }
      int gkw=(c*256+w*32+kk*16)>>1;      // word offset within W row
      #pragma unroll
      for(int nt=0;nt<4;nt++){
        int n0=nt*8+gid;
        const uint32_t* wr=(const uint32_t*)Ws+n0*516+gkw+tig;
        b[nt][0]=wr[0]; b[nt][1]=wr[4];
      }
      #pragma unroll
      for(int mt=0;mt<2;mt++)
        #pragma unroll
        for(int nt=0;nt<4;nt++) mma16(acc[mt][nt], a[mt], b[nt]);
    }
  };

  for(int t=0;t<512;t++){
    const float* gp=G+(size_t)(t*32+cb)*4096+u0+cu;
    float gpi=gp[0], gpf=gp[1024], gpg=gp[2048], gpo=gp[3072];
    int ph=t&1;
    // lanes 0-3 (warp 0, converged): poll for step readiness, then each
    // issues one chunk's TMA. Other warps proceed straight to mwait —
    // the mbarrier phase gates them.
    if(tid<4){
      if(t){ while(ldacq(cnt)<128u*(unsigned)t){} fpa(); }
      mexpect(mb+tid,16384);
      #pragma unroll
      for(int s=0;s<4;s++)
        tma2d(hs0+tid*16384+s*4096, pH, tid*256+s*64, t*32, mb+tid);
    }
    #pragma unroll
    for(int i=0;i<2;i++)
      #pragma unroll
      for(int j=0;j<4;j++)
        #pragma unroll
        for(int k=0;k<4;k++) acc[i][j][k]=0.f;
    mwait(mb+0,ph); comp(0);
    mwait(mb+1,ph); comp(1);
    mwait(mb+2,ph); comp(2);
    mwait(mb+3,ph); comp(3);

    #pragma unroll
    for(int mt=0;mt<2;mt++)
      #pragma unroll
      for(int nt=0;nt<4;nt++){
        int m=mt*16+gid, n=nt*8+tig*2;
        *(float2*)&Red[w*1024+m*32+n]    =make_float2(acc[mt][nt][0],acc[mt][nt][1]);
        *(float2*)&Red[w*1024+(m+8)*32+n]=make_float2(acc[mt][nt][2],acc[mt][nt][3]);
      }
    __syncthreads();
    {
      const float4* R4=(const float4*)Red;
      float4 s4=make_float4(0.f,0.f,0.f,0.f);
      #pragma unroll
      for(int ww=0;ww<8;ww++){ float4 v=R4[ww*256+tid]; s4.x+=v.x; s4.y+=v.y; s4.z+=v.z; s4.w+=v.w; }
      *(float4*)(Gs+(tid>>3)*36+(tid&7)*4)=s4;
    }
    __syncthreads();
    float iv=sigm(Gs[cb*36+cu]+gpi);
    float fv=sigm(Gs[cb*36+cu+8]+gpf);
    float gv=tanhf(Gs[cb*36+cu+16]+gpg);
    float ov=sigm(Gs[cb*36+cu+24]+gpo);
    creg=fv*creg+iv*gv;
    float hv=ov*tanhf(creg);
    Th[(size_t)(t+1)*32768+cb*1024+u0+cu]=__float2half_rn(hv);
    if(histf) histf[(size_t)t*32768+cb*1024+u0+cu]=hv;
    if(t==511){ hFl[cb*1024+u0+cu]=hv; cFl[cb*1024+u0+cu]=creg; }
    __syncthreads();
    if(tid==0) arrive(cnt);
  }
}

// ---------------- host ------------------------------------------------------
typedef CUresult (*EncodeFn)(CUtensorMap*, CUtensorMapDataType, cuuint32_t, void*,
                             const cuuint64_t*, const cuuint64_t*, const cuuint32_t*,
                             const cuuint32_t*, CUtensorMapInterleave, CUtensorMapSwizzle,
                             CUtensorMapL2promotion, CUtensorMapFloatOOBfill);

static EncodeFn get_encode(){
  static EncodeFn fn = nullptr;
  if(!fn){
    void* p = nullptr;
#if CUDART_VERSION >= 12050
    cudaDriverEntryPointQueryResult qr;
    cudaGetDriverEntryPointByVersion("cuTensorMapEncodeTiled", &p, 12000,
                                     cudaEnableDefault, &qr);
    if(!p) cudaGetDriverEntryPoint("cuTensorMapEncodeTiled", &p, cudaEnableDefault, &qr);
#else
    cudaGetDriverEntryPoint("cuTensorMapEncodeTiled", &p, cudaEnableDefault);
#endif
    fn = (EncodeFn)p;
  }
  return fn;
}

static void mk2dh(CUtensorMap* m, void* p, uint64_t h, uint32_t bh){
  cuuint64_t dims[2]={1024,h};
  cuuint64_t st[1]={2048};
  cuuint32_t box[2]={64,bh};
  cuuint32_t es[2]={1,1};
  get_encode()(m, CU_TENSOR_MAP_DATA_TYPE_FLOAT16, 2, p, dims, st, box, es,
    CU_TENSOR_MAP_INTERLEAVE_NONE, CU_TENSOR_MAP_SWIZZLE_128B,
    CU_TENSOR_MAP_L2_PROMOTION_L2_128B, CU_TENSOR_MAP_FLOAT_OOB_FILL_NONE);
}

extern "C" void kernel_launch(void* const* d_in, const int* in_sizes, int n_in,
                              void* d_out, int out_size){
  const int*   tok=(const int*)d_in[0];
  const float* h0 =(const float*)d_in[1];
  const float* c0 =(const float*)d_in[2];
  const float* emb=(const float*)d_in[3];
  const float* Wi0=(const float*)d_in[4];
  const float* Wh0=(const float*)d_in[5];
  const float* bi0=(const float*)d_in[6];
  const float* bh0=(const float*)d_in[7];
  const float* Wi1=(const float*)d_in[8];
  const float* Wh1=(const float*)d_in[9];
  const float* bi1=(const float*)d_in[10];
  const float* bh1=(const float*)d_in[11];
  float* out=(float*)d_out;

  void *pXH,*pG,*pT0,*pT1,*pW0,*pW1,*pWh0,*pWh1; unsigned *pc0,*pc1;
  cudaGetSymbolAddress(&pXH, g_XH);
  cudaGetSymbolAddress(&pG,  g_G);
  cudaGetSymbolAddress(&pT0, g_T0);
  cudaGetSymbolAddress(&pT1, g_T1);
  cudaGetSymbolAddress(&pW0, g_W0h);
  cudaGetSymbolAddress(&pW1, g_W1h);
  cudaGetSymbolAddress(&pWh0,g_Wh0);
  cudaGetSymbolAddress(&pWh1,g_Wh1);
  cudaGetSymbolAddress((void**)&pc0, g_cnt0);
  cudaGetSymbolAddress((void**)&pc1, g_cnt1);

  CUtensorMap mXHg, mW0g, mW1g, mT0g, mT0r, mT1r;
  mk2dh(&mXHg, pXH, 16384,128);
  mk2dh(&mW0g, pW0,  4096,128);
  mk2dh(&mW1g, pW1,  4096,128);
  mk2dh(&mT0g, pT0, 16416,128);
  mk2dh(&mT0r, pT0, 16416, 32);
  mk2dh(&mT1r, pT1, 16416, 32);

  cudaFuncSetAttribute(k_gemm, cudaFuncAttributeMaxDynamicSharedMemorySize, 99400);
  cudaFuncSetAttribute(k_rec,  cudaFuncAttributeMaxDynamicSharedMemorySize, 170100);

  float* hFb=out+16777216;   // outputs 512*32*1024
  float* cFb=out+16842752;   // + hF 2*32*1024

  k_init  <<<256,256>>>(h0);
  k_gather<<<16384,256>>>(tok, emb);
  k_prepw <<<4096,256>>>(Wi0, Wi1, Wh0, Wh1);
  k_gemm<<<dim3(32,128),256, 99400>>>(mXHg, mW0g, 0,  bi0, bh0, (float*)pG);
  k_rec <<<128,256,170100>>>(mT0r, (const __half*)pWh0, c0, (const float*)pG,
                             (__half*)pT0, nullptr, hFb, cFb, pc0);
  k_gemm<<<dim3(32,128),256, 99400>>>(mT0g, mW1g, 32, bi1, bh1, (float*)pG);
  k_rec <<<128,256,170100>>>(mT1r, (const __half*)pWh1, c0+32768, (const float*)pG,
                             (__half*)pT1, out, hFb+32768, cFb+32768, pc1);
}

// round 12
// speedup vs baseline: 1.0350x; 1.0350x over previous
#include <cuda_runtime.h>
#include <cuda.h>
#include <cuda_fp16.h>
#include <cstdint>

#define NM 16384
__device__ __half g_XH [(size_t)NM*1024];
__device__ float  g_G  [(size_t)NM*4096];
__device__ __half g_T0 [(size_t)16416*1024];        // plain layer-0 history (GEMM1 A)
__device__ __half g_P0 [(size_t)513*32768];         // permuted layer-0 history (rec TMA)
__device__ __half g_P1 [(size_t)513*32768];         // permuted layer-1 history (rec TMA)
__device__ __half g_W0h[(size_t)4096*1024];
__device__ __half g_W1h[(size_t)4096*1024];
__device__ __half g_Wh0[(size_t)4096*1024];
__device__ __half g_Wh1[(size_t)4096*1024];
__device__ unsigned g_cnt0, g_cnt1;

__device__ __forceinline__ uint32_t s32(const void* p){ return (uint32_t)__cvta_generic_to_shared(p); }
__device__ __forceinline__ void cp16(void* s, const void* g){
  asm volatile("cp.async.cg.shared.global [%0],[%1],16;"::"r"(s32(s)),"l"(g));
}
__device__ __forceinline__ void cpc(){ asm volatile("cp.async.commit_group;"); }
template<int N> __device__ __forceinline__ void cpw(){ asm volatile("cp.async.wait_group %0;"::"n"(N)); }
__device__ __forceinline__ unsigned ldacq(const unsigned* p){ unsigned v; asm volatile("ld.acquire.gpu.u32 %0,[%1];":"=r"(v):"l"(p)); return v; }
__device__ __forceinline__ void arrive(unsigned* p){ asm volatile("red.release.gpu.global.add.u32 [%0],1;"::"l"(p)); }
__device__ __forceinline__ void mbar_init(uint64_t* m, unsigned c){
  asm volatile("mbarrier.init.shared.b64 [%0],%1;"::"r"(s32(m)),"r"(c):"memory");
}
__device__ __forceinline__ void mexpect(uint64_t* m, unsigned bytes){
  asm volatile("mbarrier.arrive.expect_tx.shared.b64 _,[%0],%1;"::"r"(s32(m)),"r"(bytes):"memory");
}
__device__ __forceinline__ void mwait(uint64_t* m, int ph){
  uint32_t a=s32(m);
  asm volatile("{\n\t.reg .pred P;\nLW%=:\n\tmbarrier.try_wait.parity.shared::cta.b64 P,[%0],%1,0x989680;\n\t@P bra LD%=;\n\tbra LW%=;\nLD%=:\n\t}"::"r"(a),"r"(ph):"memory");
}
__device__ __forceinline__ void tma2d(uint32_t smem, const void* map, int x, int y, uint64_t* mb){
  asm volatile("cp.async.bulk.tensor.2d.shared::cta.global.tile.mbarrier::complete_tx::bytes [%0],[%1,{%2,%3}],[%4];"
    ::"r"(smem),"l"(map),"r"(x),"r"(y),"r"(s32(mb)):"memory");
}
__device__ __forceinline__ void fpa(){ asm volatile("fence.proxy.async;"); }
__device__ __forceinline__ void mma16(float* d, const uint32_t* a, const uint32_t* b){
  asm volatile("mma.sync.aligned.m16n8k16.row.col.f32.f16.f16.f32 {%0,%1,%2,%3},{%4,%5,%6,%7},{%8,%9},{%0,%1,%2,%3};"
    :"+f"(d[0]),"+f"(d[1]),"+f"(d[2]),"+f"(d[3])
    :"r"(a[0]),"r"(a[1]),"r"(a[2]),"r"(a[3]),"r"(b[0]),"r"(b[1]));
}
__device__ __forceinline__ float sigm(float x){ return 1.f/(1.f+__expf(-x)); }

__global__ void k_init(const float* __restrict__ h0){
  int i=blockIdx.x*256+threadIdx.x;
  if(i==0){ g_cnt0=0u; g_cnt1=0u; }
  int layer=i>>15, b=(i>>10)&31, f=i&1023;
  __half v=__float2half_rn(h0[i]);
  __half* P = layer ? g_P1 : g_P0;
  P[(size_t)(f>>6)*2048 + b*64 + (f&63)] = v;
}

__global__ void k_gather(const int* __restrict__ tok, const float* __restrict__ emb){
  size_t e=((size_t)blockIdx.x*256+threadIdx.x)*4;
  int row=(int)(e>>10), col=(int)(e&1023);
  float4 v=*(const float4*)(emb+(size_t)tok[row]*1024+col);
  __half2* p=(__half2*)(g_XH+e);
  p[0]=__floats2half2_rn(v.x,v.y); p[1]=__floats2half2_rn(v.z,v.w);
}

__global__ void k_prepw(const float* __restrict__ w0, const float* __restrict__ w1,
                        const float* __restrict__ wh0, const float* __restrict__ wh1){
  size_t e=((size_t)blockIdx.x*256+threadIdx.x)*4;
  float4 a=*(const float4*)(w0+e);
  ((__half2*)(g_W0h+e))[0]=__floats2half2_rn(a.x,a.y);
  ((__half2*)(g_W0h+e))[1]=__floats2half2_rn(a.z,a.w);
  float4 b=*(const float4*)(w1+e);
  ((__half2*)(g_W1h+e))[0]=__floats2half2_rn(b.x,b.y);
  ((__half2*)(g_W1h+e))[1]=__floats2half2_rn(b.z,b.w);
  float4 c=*(const float4*)(wh0+e);
  ((__half2*)(g_Wh0+e))[0]=__floats2half2_rn(c.x,c.y);
  ((__half2*)(g_Wh0+e))[1]=__floats2half2_rn(c.z,c.w);
  float4 d=*(const float4*)(wh1+e);
  ((__half2*)(g_Wh1+e))[0]=__floats2half2_rn(d.x,d.y);
  ((__half2*)(g_Wh1+e))[1]=__floats2half2_rn(d.z,d.w);
}

// ---- GEMM fp16: C[16384,4096] = A[16384,1024] @ W[4096,1024]^T + (b1+b2) ----
__global__ void __launch_bounds__(256,2) k_gemm(
  const __grid_constant__ CUtensorMap mA, const __grid_constant__ CUtensorMap mW,
  int yoff, const float* __restrict__ b1, const float* __restrict__ b2,
  float* __restrict__ C){
  extern __shared__ char smraw[];
  char* base=(char*)((((uintptr_t)smraw)+1023)&~(uintptr_t)1023);
  uint32_t* sA=(uint32_t*)base;            // 3 x 16KB (128 rows x 64 halves)
  uint32_t* sB=(uint32_t*)(base+49152);    // 3 x 16KB
  uint64_t* mb=(uint64_t*)(base+98304);
  const int tid=threadIdx.x, lane=tid&31, wid=tid>>5;
  const int wm=wid>>1, wn=wid&1, gid=lane>>2, tig=lane&3;
  const int bm=blockIdx.y, bn=blockIdx.x;
  const void* pA=(const void*)&mA; const void* pW=(const void*)&mW;
  uint32_t sa0=s32(sA), sb0=s32(sB);
  if(tid==0){ mbar_init(mb+0,1); mbar_init(mb+1,1); mbar_init(mb+2,1); fpa(); }
  __syncthreads();
  auto issue=[&](int ks){
    if(tid==0){
      int s=ks%3;
      mexpect(mb+s,32768);
      tma2d(sa0+s*16384, pA, ks*64, bm*128+yoff, mb+s);
      tma2d(sb0+s*16384, pW, ks*64, bn*128,      mb+s);
    }
  };
  issue(0); issue(1); issue(2);
  float acc[2][8][4];
  #pragma unroll
  for(int i=0;i<2;i++)
    #pragma unroll
    for(int j=0;j<8;j++)
      #pragma unroll
      for(int k=0;k<4;k++) acc[i][j][k]=0.f;
  for(int ks=0;ks<16;ks++){
    int s=ks%3;
    mwait(mb+s,(ks/3)&1);
    const uint32_t* cA=sA+s*4096; const uint32_t* cB=sB+s*4096;
    #pragma unroll
    for(int kk=0;kk<4;kk++){
      int c0=(((kk*2)^gid)<<2)+tig, c1=(((kk*2+1)^gid)<<2)+tig;
      uint32_t a[2][4], b[8][2];
      #pragma unroll
      for(int mt=0;mt<2;mt++){
        int r0=wm*32+mt*16+gid;
        a[mt][0]=cA[r0*32+c0]; a[mt][1]=cA[(r0+8)*32+c0];
        a[mt][2]=cA[r0*32+c1]; a[mt][3]=cA[(r0+8)*32+c1];
      }
      #pragma unroll
      for(int nt=0;nt<8;nt++){
        int n0=wn*64+nt*8+gid;
        b[nt][0]=cB[n0*32+c0]; b[nt][1]=cB[n0*32+c1];
      }
      #pragma unroll
      for(int mt=0;mt<2;mt++)
        #pragma unroll
        for(int nt=0;nt<8;nt++) mma16(acc[mt][nt], a[mt], b[nt]);
    }
    __syncthreads();
    if(ks+3<16) issue(ks+3);
  }
  #pragma unroll
  for(int nt=0;nt<8;nt++){
    int n=bn*128+wn*64+nt*8+tig*2;
    float bb0=b1[n]+b2[n], bb1=b1[n+1]+b2[n+1];
    #pragma unroll
    for(int mt=0;mt<2;mt++){
      size_t m0=(size_t)bm*128+wm*32+mt*16+gid;
      *(float2*)(C+m0*4096+n)    =make_float2(acc[mt][nt][0]+bb0, acc[mt][nt][1]+bb1);
      *(float2*)(C+(m0+8)*4096+n)=make_float2(acc[mt][nt][2]+bb0, acc[mt][nt][3]+bb1);
    }
  }
}

// ---- persistent recurrence (fp16, permuted-history TMA: 4 big loads) -------
__global__ void __launch_bounds__(256,1) k_rec(
  const __grid_constant__ CUtensorMap mH,
  const __half* __restrict__ Whh, const float* __restrict__ c0l,
  const float* __restrict__ G,
  __half* __restrict__ Tp,        // permuted history (always written)
  __half* __restrict__ Tpl,       // plain history (layer 0 only, for GEMM1)
  float* __restrict__ histf,      // fp32 outputs (layer 1 only)
  float* __restrict__ hFl, float* __restrict__ cFl, unsigned* cnt){
  extern __shared__ char smraw[];
  char* base=(char*)((((uintptr_t)smraw)+1023)&~(uintptr_t)1023);
  uint32_t* Hs=(uint32_t*)base;            // 3 x 16KB h buffers
  __half*   Ws=(__half*)(base+49152);      // 32 x 1032 halves (66048B)
  float*    Red=(float*)(base+115200);     // 32KB
  float*    Gs =(float*)(base+147968);     // 32 x 33 floats
  uint64_t* mb =(uint64_t*)(base+152192);  // 4 mbarriers
  const int tid=threadIdx.x, lane=tid&31, w=tid>>5;
  const int gid=lane>>2, tig=lane&3, u0=blockIdx.x*8;
  const int cb=tid>>3, cu=tid&7;
  const void* pH=(const void*)&mH;
  uint32_t hs0=s32(Hs);

  if(tid==0){
    mbar_init(mb+0,1); mbar_init(mb+1,1); mbar_init(mb+2,1); mbar_init(mb+3,1);
    fpa();
  }
  #pragma unroll 4
  for(int i=0;i<16;i++){
    int idx=i*256+tid, r=idx>>7, q=idx&127;
    cp16(Ws+r*1032+q*8, Whh+(size_t)((r>>3)*1024+u0+(r&7))*1024+q*8);
  }
  cpc(); cpw<0>();
  float creg=c0l[cb*1024+u0+cu];
  __syncthreads();

  float acc[2][4][4];
  auto comp=[&](int c){
    const uint32_t* Hc=Hs+(c%3)*4096;     // words
    #pragma unroll
    for(int kk=0;kk<2;kk++){
      int q=2*w+kk, s=q>>2, off=(q&3)*2;
      int c0=((off^gid)<<2)+tig, c1=(((off+1)^gid)<<2)+tig;
      uint32_t a[2][4], b[4][2];
      #pragma unroll
      for(int mt=0;mt<2;mt++){
        int r0=mt*16+gid;
        a[mt][0]=Hc[s*1024+r0*32+c0]; a[mt][1]=Hc[s*1024+(r0+8)*32+c0];
        a[mt][2]=Hc[s*1024+r0*32+c1]; a[mt][3]=Hc[s*1024+(r0+8)*32+c1];
      }
      int gkw=(c*256+w*32+kk*16)>>1;      // word offset within W row
      #pragma unroll
      for(int nt=0;nt<4;nt++){
        int n0=nt*8+gid;
        const uint32_t* wr=(const uint32_t*)Ws+n0*516+gkw+tig;
        b[nt][0]=wr[0]; b[nt][1]=wr[4];
      }
      #pragma unroll
      for(int mt=0;mt<2;mt++)
        #pragma unroll
        for(int nt=0;nt<4;nt++) mma16(acc[mt][nt], a[mt], b[nt]);
    }
  };

  for(int t=0;t<512;t++){
    const float* gp=G+(size_t)(t*32+cb)*4096+u0+cu;
    float gpi=gp[0], gpf=gp[1024], gpg=gp[2048], gpo=gp[3072];
    if(t && tid==0){
      while(ldacq(cnt)<128u*(unsigned)t) __nanosleep(20);
      fpa();
    }
    __syncthreads();
    int ph=t&1;
    if(tid==0){
      // one 16KB TMA per buffer (box 64x128 over the permuted history)
      #pragma unroll
      for(int c=0;c<3;c++){
        mexpect(mb+c,16384);
        tma2d(hs0+c*16384, pH, 0, t*512+c*128, mb+c);
      }
    }
    #pragma unroll
    for(int i=0;i<2;i++)
      #pragma unroll
      for(int j=0;j<4;j++)
        #pragma unroll
        for(int k=0;k<4;k++) acc[i][j][k]=0.f;
    mwait(mb+0,ph); comp(0);
    __syncthreads();                  // all warps done reading buffer 0
    if(tid==0){
      mexpect(mb+3,16384);
      tma2d(hs0, pH, 0, t*512+384, mb+3);
    }
    mwait(mb+1,ph); comp(1);
    mwait(mb+2,ph); comp(2);
    mwait(mb+3,ph); comp(3);

    #pragma unroll
    for(int mt=0;mt<2;mt++)
      #pragma unroll
      for(int nt=0;nt<4;nt++){
        int m=mt*16+gid, n=nt*8+tig*2;
        Red[w*1024+m*32+n]    =acc[mt][nt][0]; Red[w*1024+m*32+n+1]    =acc[mt][nt][1];
        Red[w*1024+(m+8)*32+n]=acc[mt][nt][2]; Red[w*1024+(m+8)*32+n+1]=acc[mt][nt][3];
      }
    __syncthreads();
    {
      const float4* R4=(const float4*)Red;
      float4 s4=make_float4(0.f,0.f,0.f,0.f);
      #pragma unroll
      for(int ww=0;ww<8;ww++){ float4 v=R4[ww*256+tid]; s4.x+=v.x; s4.y+=v.y; s4.z+=v.z; s4.w+=v.w; }
      float* gdst=Gs+(tid>>3)*33+(tid&7)*4;
      gdst[0]=s4.x; gdst[1]=s4.y; gdst[2]=s4.z; gdst[3]=s4.w;
    }
    __syncthreads();
    float iv=sigm(Gs[cb*33+cu]+gpi);
    float fv=sigm(Gs[cb*33+cu+8]+gpf);
    float gv=tanhf(Gs[cb*33+cu+16]+gpg);
    float ov=sigm(Gs[cb*33+cu+24]+gpo);
    creg=fv*creg+iv*gv;
    float hv=ov*tanhf(creg);
    int f=u0+cu;
    __half hh=__float2half_rn(hv);
    Tp[(size_t)(t+1)*32768 + (f>>6)*2048 + cb*64 + (f&63)] = hh;
    if(Tpl)   Tpl[(size_t)(t+1)*32768 + cb*1024 + f] = hh;
    if(histf) histf[(size_t)t*32768 + cb*1024 + f] = hv;
    if(t==511){ hFl[cb*1024+f]=hv; cFl[cb*1024+f]=creg; }
    __syncthreads();
    if(tid==0) arrive(cnt);
  }
}

// ---------------- host ------------------------------------------------------
typedef CUresult (*EncodeFn)(CUtensorMap*, CUtensorMapDataType, cuuint32_t, void*,
                             const cuuint64_t*, const cuuint64_t*, const cuuint32_t*,
                             const cuuint32_t*, CUtensorMapInterleave, CUtensorMapSwizzle,
                             CUtensorMapL2promotion, CUtensorMapFloatOOBfill);

static EncodeFn get_encode(){
  static EncodeFn fn = nullptr;
  if(!fn){
    void* p = nullptr;
#if CUDART_VERSION >= 12050
    cudaDriverEntryPointQueryResult qr;
    cudaGetDriverEntryPointByVersion("cuTensorMapEncodeTiled", &p, 12000,
                                     cudaEnableDefault, &qr);
    if(!p) cudaGetDriverEntryPoint("cuTensorMapEncodeTiled", &p, cudaEnableDefault, &qr);
#else
    cudaGetDriverEntryPoint("cuTensorMapEncodeTiled", &p, cudaEnableDefault);
#endif
    fn = (EncodeFn)p;
  }
  return fn;
}

static void mk2dh(CUtensorMap* m, void* p, uint64_t h, uint32_t bh){
  cuuint64_t dims[2]={1024,h};
  cuuint64_t st[1]={2048};
  cuuint32_t box[2]={64,bh};
  cuuint32_t es[2]={1,1};
  get_encode()(m, CU_TENSOR_MAP_DATA_TYPE_FLOAT16, 2, p, dims, st, box, es,
    CU_TENSOR_MAP_INTERLEAVE_NONE, CU_TENSOR_MAP_SWIZZLE_128B,
    CU_TENSOR_MAP_L2_PROMOTION_L2_128B, CU_TENSOR_MAP_FLOAT_OOB_FILL_NONE);
}

// permuted history map: rows of 64 halves (128B), 513*512 rows, box 64x128
static void mk2dp(CUtensorMap* m, void* p){
  cuuint64_t dims[2]={64, 513ull*512ull};
  cuuint64_t st[1]={128};
  cuuint32_t box[2]={64,128};
  cuuint32_t es[2]={1,1};
  get_encode()(m, CU_TENSOR_MAP_DATA_TYPE_FLOAT16, 2, p, dims, st, box, es,
    CU_TENSOR_MAP_INTERLEAVE_NONE, CU_TENSOR_MAP_SWIZZLE_128B,
    CU_TENSOR_MAP_L2_PROMOTION_L2_128B, CU_TENSOR_MAP_FLOAT_OOB_FILL_NONE);
}

extern "C" void kernel_launch(void* const* d_in, const int* in_sizes, int n_in,
                              void* d_out, int out_size){
  const int*   tok=(const int*)d_in[0];
  const float* h0 =(const float*)d_in[1];
  const float* c0 =(const float*)d_in[2];
  const float* emb=(const float*)d_in[3];
  const float* Wi0=(const float*)d_in[4];
  const float* Wh0=(const float*)d_in[5];
  const float* bi0=(const float*)d_in[6];
  const float* bh0=(const float*)d_in[7];
  const float* Wi1=(const float*)d_in[8];
  const float* Wh1=(const float*)d_in[9];
  const float* bi1=(const float*)d_in[10];
  const float* bh1=(const float*)d_in[11];
  float* out=(float*)d_out;

  void *pXH,*pG,*pT0,*pP0,*pP1,*pW0,*pW1,*pWh0,*pWh1; unsigned *pc0,*pc1;
  cudaGetSymbolAddress(&pXH, g_XH);
  cudaGetSymbolAddress(&pG,  g_G);
  cudaGetSymbolAddress(&pT0, g_T0);
  cudaGetSymbolAddress(&pP0, g_P0);
  cudaGetSymbolAddress(&pP1, g_P1);
  cudaGetSymbolAddress(&pW0, g_W0h);
  cudaGetSymbolAddress(&pW1, g_W1h);
  cudaGetSymbolAddress(&pWh0,g_Wh0);
  cudaGetSymbolAddress(&pWh1,g_Wh1);
  cudaGetSymbolAddress((void**)&pc0, g_cnt0);
  cudaGetSymbolAddress((void**)&pc1, g_cnt1);

  CUtensorMap mXHg, mW0g, mW1g, mT0g, mP0r, mP1r;
  mk2dh(&mXHg, pXH, 16384,128);
  mk2dh(&mW0g, pW0,  4096,128);
  mk2dh(&mW1g, pW1,  4096,128);
  mk2dh(&mT0g, pT0, 16416,128);
  mk2dp(&mP0r, pP0);
  mk2dp(&mP1r, pP1);

  cudaFuncSetAttribute(k_gemm, cudaFuncAttributeMaxDynamicSharedMemorySize, 99400);
  cudaFuncSetAttribute(k_rec,  cudaFuncAttributeMaxDynamicSharedMemorySize, 153400);

  float* hFb=out+16777216;   // outputs 512*32*1024
  float* cFb=out+16842752;   // + hF 2*32*1024

  k_init  <<<256,256>>>(h0);
  k_gather<<<16384,256>>>(tok, emb);
  k_prepw <<<4096,256>>>(Wi0, Wi1, Wh0, Wh1);
  k_gemm<<<dim3(32,128),256, 99400>>>(mXHg, mW0g, 0,  bi0, bh0, (float*)pG);
  k_rec <<<128,256,153400>>>(mP0r, (const __half*)pWh0, c0, (const float*)pG,
                             (__half*)pP0, (__half*)pT0, nullptr, hFb, cFb, pc0);
  k_gemm<<<dim3(32,128),256, 99400>>>(mT0g, mW1g, 32, bi1, bh1, (float*)pG);
  k_rec <<<128,256,153400>>>(mP1r, (const __half*)pWh1, c0+32768, (const float*)pG,
                             (__half*)pP1, nullptr, out, hFb+32768, cFb+32768, pc1);
}